// round 1
// baseline (speedup 1.0000x reference)
#include <cuda_runtime.h>
#include <cuda_bf16.h>

// LambdaLoss: loss = sum_{i,j} sigmoid(-(sp_i - sp_j)) * |(st_i-st_j)(disc_j-disc_i)| / B
// Identity: sigma(x)+sigma(-x)=1 and delta symmetric => loss = (1/B) * sum_{i<j} delta_ij
// Pairs are over unordered elements, so only each element's rank matters:
//   dv_a = log2(rank0_a + 3),  loss = (1/(2B)) * sum_b sum_{a,a'} |t_a - t_a'| * |dv_a - dv_a'|

constexpr int BB = 32;
constexpr int NN = 2048;
constexpr int TPB = 128;          // threads per block
constexpr int CHUNKS = NN / TPB;  // 16 chunks per row

__device__ float g_dv[BB * NN];   // per-element discount value

__global__ void zero_kernel(float* out) {
    if (threadIdx.x == 0) out[0] = 0.0f;
}

// Stable rank of each element within its row (descending preds, ties keep index order),
// then dv = log2(rank0 + 3).
__global__ void __launch_bounds__(TPB) rank_kernel(const float* __restrict__ preds) {
    __shared__ float sp[NN];
    const int row = blockIdx.y;
    const float* p = preds + row * NN;
    for (int k = threadIdx.x; k < NN; k += TPB) sp[k] = p[k];
    __syncthreads();

    const int a = blockIdx.x * TPB + threadIdx.x;
    const float pa = sp[a];
    int cnt = 0;
#pragma unroll 8
    for (int j = 0; j < NN; j++) {
        float pj = sp[j];
        // comes-before in stable descending sort of preds
        cnt += (pj > pa) || (pj == pa && j < a);
    }
    g_dv[row * NN + a] = log2f((float)(cnt + 3));
}

// S_row = sum over all ordered pairs (a, j) of |t_a - t_j| * |dv_a - dv_j|
// loss contribution per block: block_sum * 0.5 / B  (0.5 undoes double counting)
__global__ void __launch_bounds__(TPB) pair_kernel(const float* __restrict__ targets,
                                                   float* __restrict__ out) {
    __shared__ float2 td[NN];     // (target, dv) interleaved for single LDS.64
    const int row = blockIdx.y;
    const float* t  = targets + row * NN;
    const float* dv = g_dv    + row * NN;
    for (int k = threadIdx.x; k < NN; k += TPB)
        td[k] = make_float2(t[k], dv[k]);
    __syncthreads();

    const int a = blockIdx.x * TPB + threadIdx.x;
    const float ta = td[a].x;
    const float da = td[a].y;

    float acc0 = 0.f, acc1 = 0.f, acc2 = 0.f, acc3 = 0.f;
#pragma unroll 4
    for (int j = 0; j < NN; j += 4) {
        float2 v0 = td[j + 0];
        float2 v1 = td[j + 1];
        float2 v2 = td[j + 2];
        float2 v3 = td[j + 3];
        acc0 += fabsf(ta - v0.x) * fabsf(da - v0.y);
        acc1 += fabsf(ta - v1.x) * fabsf(da - v1.y);
        acc2 += fabsf(ta - v2.x) * fabsf(da - v2.y);
        acc3 += fabsf(ta - v3.x) * fabsf(da - v3.y);
    }
    float s = (acc0 + acc1) + (acc2 + acc3);

    // warp reduction
#pragma unroll
    for (int off = 16; off > 0; off >>= 1)
        s += __shfl_down_sync(0xffffffffu, s, off);

    __shared__ float warp_sums[TPB / 32];
    if ((threadIdx.x & 31) == 0) warp_sums[threadIdx.x >> 5] = s;
    __syncthreads();
    if (threadIdx.x == 0) {
        float bs = 0.f;
#pragma unroll
        for (int w = 0; w < TPB / 32; w++) bs += warp_sums[w];
        atomicAdd(out, bs * (0.5f / (float)BB));
    }
}

extern "C" void kernel_launch(void* const* d_in, const int* in_sizes, int n_in,
                              void* d_out, int out_size) {
    const float* preds   = (const float*)d_in[0];
    const float* targets = (const float*)d_in[1];
    float* out = (float*)d_out;

    zero_kernel<<<1, 32>>>(out);

    dim3 grid(CHUNKS, BB);
    rank_kernel<<<grid, TPB>>>(preds);
    pair_kernel<<<grid, TPB>>>(targets, out);
}

// round 2
// speedup vs baseline: 1.2746x; 1.2746x over previous
#include <cuda_runtime.h>
#include <cuda_bf16.h>

// LambdaLoss restructured:
//   sigma(x)+sigma(-x)=1 and delta symmetric  =>  loss = (1/B) * sum_{i<j} delta_ij
//   delta depends only on (target, pred-rank) pairs:
//     loss = (1/(2B)) * sum_b sum_{a,a'} |t_a - t_a'| * |dv_a - dv_a'|,  dv = log2(rank0+3)
// Kernel 1: per-row bitonic sort by (pred desc, idx asc) carrying target
//           -> sorted_targets; dv in sorted order is the CONSTANT array log2(k+3).
// Kernel 2: brute-force pair sum, 8 a-values per thread, packed f32x2 math.

constexpr int BB = 32;
constexpr int NN = 2048;
constexpr int TPB = 128;     // pair kernel threads
constexpr int AV = 8;        // a-values per thread
constexpr int JSPLIT = 4;    // j-range split per a-chunk
constexpr int ACH = NN / (TPB * AV);   // 2 a-chunks
constexpr int JLEN = NN / JSPLIT;      // 512 j per block

typedef unsigned long long ull;

__device__ float g_st[BB * NN];   // targets permuted into pred-rank order

// ---------- packed f32x2 helpers ----------
__device__ __forceinline__ ull pk2(float lo, float hi) {
    ull r; asm("mov.b64 %0, {%1, %2};" : "=l"(r) : "f"(lo), "f"(hi)); return r;
}
__device__ __forceinline__ void upk2(float& lo, float& hi, ull v) {
    asm("mov.b64 {%0, %1}, %2;" : "=f"(lo), "=f"(hi) : "l"(v));
}
__device__ __forceinline__ ull add2(ull a, ull b) {
    ull r; asm("add.rn.f32x2 %0, %1, %2;" : "=l"(r) : "l"(a), "l"(b)); return r;
}
__device__ __forceinline__ ull mul2(ull a, ull b) {
    ull r; asm("mul.rn.f32x2 %0, %1, %2;" : "=l"(r) : "l"(a), "l"(b)); return r;
}

// ---------- kernel 1: bitonic sort per row ----------
__global__ void __launch_bounds__(1024) sort_kernel(const float* __restrict__ preds,
                                                    const float* __restrict__ targets,
                                                    float* __restrict__ out) {
    __shared__ ull   sk[NN];
    __shared__ float sv[NN];
    const int row = blockIdx.x;
    if (row == 0 && threadIdx.x == 0) out[0] = 0.0f;   // runs before pair kernel (stream order)

    const float* p = preds + row * NN;
    const float* t = targets + row * NN;
    for (int i = threadIdx.x; i < NN; i += 1024) {
        unsigned u = __float_as_uint(p[i]);
        u = (u & 0x80000000u) ? ~u : (u | 0x80000000u);  // monotone asc over floats
        u = ~u;                                           // descending preds
        sk[i] = ((ull)u << 32) | (unsigned)i;             // stable: idx in low bits
        sv[i] = t[i];
    }
    for (int k = 2; k <= NN; k <<= 1) {
        for (int j = k >> 1; j > 0; j >>= 1) {
            __syncthreads();
            int tid = threadIdx.x;                        // 1024 compare pairs
            int i   = ((tid & ~(j - 1)) << 1) | (tid & (j - 1));
            int ixj = i | j;
            ull ki = sk[i], kj = sk[ixj];
            bool up = ((i & k) == 0);
            if ((ki > kj) == up) {                        // keys unique (idx tie-break)
                sk[i] = kj; sk[ixj] = ki;
                float vi = sv[i], vj = sv[ixj];
                sv[i] = vj; sv[ixj] = vi;
            }
        }
    }
    __syncthreads();
    for (int i = threadIdx.x; i < NN; i += 1024)
        g_st[row * NN + i] = sv[i];
}

// ---------- kernel 2: pair sum ----------
__global__ void __launch_bounds__(TPB) pair_kernel(float* __restrict__ out) {
    __shared__ float ss[NN];   // sorted targets (SoA, enables packed LDS.64 of 2 j's)
    __shared__ float dd[NN];   // dv constants

    const int row = blockIdx.y;
    const int ac  = blockIdx.x & (ACH - 1);        // a-chunk
    const int jb  = blockIdx.x >> 1;               // j-split index (ACH==2)

    const float* st = g_st + row * NN;
    for (int i = threadIdx.x; i < NN; i += TPB) {
        ss[i] = st[i];
        dd[i] = __log2f((float)(i + 3));
    }
    __syncthreads();

    // 8 a-values per thread, strided across the chunk
    ull nsa[AV], nda[AV], acc[AV];
#pragma unroll
    for (int v = 0; v < AV; v++) {
        int a = ac * (TPB * AV) + v * TPB + threadIdx.x;
        float sa = ss[a], da = dd[a];
        nsa[v] = pk2(-sa, -sa);
        nda[v] = pk2(-da, -da);
        acc[v] = 0ull;
    }

    const ull amask = 0x7fffffff7fffffffULL;
    const int j0 = jb * JLEN;
#pragma unroll 4
    for (int j = j0; j < j0 + JLEN; j += 2) {
        ull sj = *(const ull*)&ss[j];   // (s_j, s_j+1) packed
        ull dj = *(const ull*)&dd[j];   // (d_j, d_j+1) packed
#pragma unroll
        for (int v = 0; v < AV; v++) {
            ull dt = add2(sj, nsa[v]);          // t_j - t_a  (x2)
            ull dm = add2(dj, nda[v]);          // dv_j - dv_a (x2)
            ull pr = mul2(dt, dm);
            acc[v] = add2(acc[v], pr & amask);  // += |dt*dm| (x2)
        }
    }

    float s = 0.f;
#pragma unroll
    for (int v = 0; v < AV; v++) {
        float lo, hi; upk2(lo, hi, acc[v]);
        s += lo + hi;
    }
#pragma unroll
    for (int off = 16; off > 0; off >>= 1)
        s += __shfl_down_sync(0xffffffffu, s, off);

    __shared__ float wsum[TPB / 32];
    if ((threadIdx.x & 31) == 0) wsum[threadIdx.x >> 5] = s;
    __syncthreads();
    if (threadIdx.x == 0) {
        float bs = 0.f;
#pragma unroll
        for (int w = 0; w < TPB / 32; w++) bs += wsum[w];
        atomicAdd(out, bs * (0.5f / (float)BB));
    }
}

extern "C" void kernel_launch(void* const* d_in, const int* in_sizes, int n_in,
                              void* d_out, int out_size) {
    const float* preds   = (const float*)d_in[0];
    const float* targets = (const float*)d_in[1];
    float* out = (float*)d_out;

    sort_kernel<<<BB, 1024>>>(preds, targets, out);

    dim3 grid(ACH * JSPLIT, BB);
    pair_kernel<<<grid, TPB>>>(out);
}

// round 3
// speedup vs baseline: 1.5607x; 1.2244x over previous
#include <cuda_runtime.h>
#include <cuda_bf16.h>

// LambdaLoss restructured:
//   sigma(x)+sigma(-x)=1 and symmetric deltas  =>  loss = (1/(2B)) * sum_b sum_{a,j} |t_a-t_j|*|dv_a-dv_j|
// where elements are in descending-pred rank order and dv_k = log2(k+3) (MONOTONE INCREASING).
// Kernel 1: hybrid bitonic sort of packed (pred-key<<32 | target-bits) -> sorted targets.
// Kernel 2: per-thread a, split j-loop at a so |dv_a-dv_j| needs no abs:
//   res = (h1 - dv_a*h0) + (dv_a*l0 - l1),  u = |t_j - t_a| packed f32x2, 3 FMA-instr per 2 pairs.

constexpr int BB = 32;
constexpr int NN = 2048;

typedef unsigned long long ull;

__device__ float g_st[BB * NN];   // targets permuted into pred-rank order

// ---------- packed f32x2 helpers ----------
__device__ __forceinline__ ull pk2(float lo, float hi) {
    ull r; asm("mov.b64 %0, {%1, %2};" : "=l"(r) : "f"(lo), "f"(hi)); return r;
}
__device__ __forceinline__ float sum2(ull v) {
    float lo, hi; asm("mov.b64 {%0, %1}, %2;" : "=f"(lo), "=f"(hi) : "l"(v));
    return lo + hi;
}
__device__ __forceinline__ ull add2(ull a, ull b) {
    ull r; asm("add.rn.f32x2 %0, %1, %2;" : "=l"(r) : "l"(a), "l"(b)); return r;
}
__device__ __forceinline__ ull fma2(ull a, ull b, ull c) {
    ull r; asm("fma.rn.f32x2 %0, %1, %2, %3;" : "=l"(r) : "l"(a), "l"(b), "l"(c)); return r;
}
__device__ __forceinline__ ull abs2(ull a) { return a & 0x7fffffff7fffffffULL; }

// ---------- kernel 1: hybrid bitonic sort per row ----------
__device__ __forceinline__ ull cex(ull v, ull o, int p, int j, int k) {
    bool up  = ((p & k) == 0);
    bool low = ((p & j) == 0);
    ull mn = (v < o) ? v : o;
    ull mx = (v < o) ? o : v;
    return (low == up) ? mn : mx;
}

__global__ void __launch_bounds__(1024) sort_kernel(const float* __restrict__ preds,
                                                    const float* __restrict__ targets,
                                                    float* __restrict__ out) {
    __shared__ ull sm[NN];
    const int row = blockIdx.x;
    const int t = threadIdx.x;
    if (row == 0 && t == 0) out[0] = 0.0f;   // stream order: before pair_kernel

    const float* p  = preds + row * NN;
    const float* tv = targets + row * NN;

    // packed element: hi 32 = monotone key for DESCENDING pred, lo 32 = target payload
    unsigned u0 = __float_as_uint(p[t]);
    u0 = (u0 & 0x80000000u) ? ~u0 : (u0 | 0x80000000u);
    ull v0 = ((ull)(~u0) << 32) | (ull)__float_as_uint(tv[t]);
    unsigned u1 = __float_as_uint(p[t + 1024]);
    u1 = (u1 & 0x80000000u) ? ~u1 : (u1 | 0x80000000u);
    ull v1 = ((ull)(~u1) << 32) | (ull)__float_as_uint(tv[t + 1024]);

#pragma unroll
    for (int k = 2; k <= NN; k <<= 1) {
#pragma unroll
        for (int j = k >> 1; j > 0; j >>= 1) {
            if (j == 1024) {
                // partner of position t is t+1024: both local to this thread; dir ascending
                ull mn = (v0 < v1) ? v0 : v1;
                ull mx = (v0 < v1) ? v1 : v0;
                v0 = mn; v1 = mx;
            } else if (j >= 32) {
                __syncthreads();
                sm[t] = v0; sm[t + 1024] = v1;
                __syncthreads();
                ull o0 = sm[t ^ j];
                ull o1 = sm[(t + 1024) ^ j];
                v0 = cex(v0, o0, t, j, k);
                v1 = cex(v1, o1, t + 1024, j, k);
            } else {
                ull o0 = __shfl_xor_sync(0xffffffffu, v0, j);
                v0 = cex(v0, o0, t, j, k);
                ull o1 = __shfl_xor_sync(0xffffffffu, v1, j);
                v1 = cex(v1, o1, t + 1024, j, k);
            }
        }
    }
    g_st[row * NN + t]        = __uint_as_float((unsigned)v0);
    g_st[row * NN + t + 1024] = __uint_as_float((unsigned)v1);
}

// ---------- kernel 2: pair sum with sign-split (dv monotone) ----------
constexpr int TPB2 = 256;
constexpr int ACH2 = NN / TPB2;   // 8 a-chunks
constexpr int JH   = 2;           // j halves
constexpr int JL   = NN / JH;     // 1024

__global__ void __launch_bounds__(TPB2) pair_kernel(float* __restrict__ out) {
    __shared__ alignas(16) float ss[NN];
    __shared__ alignas(16) float dd[NN];

    const int row = blockIdx.y;
    const int ac  = blockIdx.x & (ACH2 - 1);
    const int jh  = blockIdx.x >> 3;

    const float* st = g_st + row * NN;
    for (int i = threadIdx.x; i < NN; i += TPB2) {
        ss[i] = st[i];
        dd[i] = __log2f((float)(i + 3));
    }
    __syncthreads();

    const int a = ac * TPB2 + threadIdx.x;
    const float ta = ss[a];
    const float da = dd[a];
    const ull nta = pk2(-ta, -ta);

    const int j0 = jh * JL, j1 = j0 + JL;
    const int A  = a & ~1;
    const int lo_e = min(A, j1);
    const int hi_b = max(A, j0);

    const ull* ps = (const ull*)ss;
    const ull* pd = (const ull*)dd;

    ull l0 = 0, l1 = 0, h0 = 0, h1 = 0;
#pragma unroll 4
    for (int j = (j0 >> 1); j < (lo_e >> 1); j++) {
        ull u = abs2(add2(ps[j], nta));   // |t_j - t_a| x2
        l1 = fma2(u, pd[j], l1);
        l0 = add2(l0, u);
    }
#pragma unroll 4
    for (int j = (hi_b >> 1); j < (j1 >> 1); j++) {
        ull u = abs2(add2(ps[j], nta));
        h1 = fma2(u, pd[j], h1);
        h0 = add2(h0, u);
    }

    // j<a: u*(da-dvj) summed = da*l0 - l1 ; j>a: u*(dvj-da) summed = h1 - da*h0
    float res = (sum2(h1) - sum2(l1)) + da * (sum2(l0) - sum2(h0));

    // straddling pair: odd a put j=a-1 into hi-loop with flipped sign; fix exactly
    if ((a & 1) && A >= j0 && A < j1) {
        float u = fabsf(ss[A] - ta);
        res += 2.0f * u * (da - dd[A]);
    }

    // block reduction
#pragma unroll
    for (int off = 16; off > 0; off >>= 1)
        res += __shfl_down_sync(0xffffffffu, res, off);

    __shared__ float wsum[TPB2 / 32];
    if ((threadIdx.x & 31) == 0) wsum[threadIdx.x >> 5] = res;
    __syncthreads();
    if (threadIdx.x == 0) {
        float bs = 0.f;
#pragma unroll
        for (int w = 0; w < TPB2 / 32; w++) bs += wsum[w];
        atomicAdd(out, bs * (0.5f / (float)BB));
    }
}

extern "C" void kernel_launch(void* const* d_in, const int* in_sizes, int n_in,
                              void* d_out, int out_size) {
    const float* preds   = (const float*)d_in[0];
    const float* targets = (const float*)d_in[1];
    float* out = (float*)d_out;

    sort_kernel<<<BB, 1024>>>(preds, targets, out);

    dim3 grid(ACH2 * JH, BB);
    pair_kernel<<<grid, TPB2>>>(out);
}

// round 4
// speedup vs baseline: 2.3231x; 1.4885x over previous
#include <cuda_runtime.h>
#include <cuda_bf16.h>

// LambdaLoss restructured:
//   sigma(x)+sigma(-x)=1, symmetric deltas => loss = (1/B) * sum_b sum_{unordered pairs} |t_p-t_q|*|dv_p-dv_q|
// with elements in descending-pred rank order and dv_k = log2(k+3) (monotone increasing in k).
// Kernel 1: hybrid bitonic sort (regs/shfl/double-buffered smem) of packed (pred-key<<32|target).
// Kernel 2: triangle-tiled pair sum: 256x256 tiles, upper triangle only; off-diag tiles need no
//           abs on dv (index-monotone); diag tiles use sign-split, scaled 0.5. Packed f32x2 + LDS.128.

constexpr int BB = 32;
constexpr int NN = 2048;
constexpr int TS = 256;          // tile size
constexpr int NT = NN / TS;      // 8 tiles per dim
constexpr int NTILES = NT * (NT + 1) / 2;  // 36

typedef unsigned long long ull;

__device__ float g_st[BB * NN];  // targets permuted into pred-rank order

// ---------- packed f32x2 helpers ----------
__device__ __forceinline__ ull pk2(float lo, float hi) {
    ull r; asm("mov.b64 %0, {%1, %2};" : "=l"(r) : "f"(lo), "f"(hi)); return r;
}
__device__ __forceinline__ float sum2(ull v) {
    float lo, hi; asm("mov.b64 {%0, %1}, %2;" : "=f"(lo), "=f"(hi) : "l"(v));
    return lo + hi;
}
__device__ __forceinline__ ull add2(ull a, ull b) {
    ull r; asm("add.rn.f32x2 %0, %1, %2;" : "=l"(r) : "l"(a), "l"(b)); return r;
}
__device__ __forceinline__ ull fma2(ull a, ull b, ull c) {
    ull r; asm("fma.rn.f32x2 %0, %1, %2, %3;" : "=l"(r) : "l"(a), "l"(b), "l"(c)); return r;
}
__device__ __forceinline__ ull abs2(ull a) { return a & 0x7fffffff7fffffffULL; }

// ---------- kernel 1: hybrid bitonic sort per row ----------
__device__ __forceinline__ ull cex(ull v, ull o, int p, int j, int k) {
    bool up  = ((p & k) == 0);
    bool low = ((p & j) == 0);
    ull mn = (v < o) ? v : o;
    ull mx = (v < o) ? o : v;
    return (low == up) ? mn : mx;
}

__global__ void __launch_bounds__(1024) sort_kernel(const float* __restrict__ preds,
                                                    const float* __restrict__ targets,
                                                    float* __restrict__ out) {
    __shared__ ull sm[2][NN];    // double buffer: 1 barrier per smem stage
    const int row = blockIdx.x;
    const int t = threadIdx.x;
    if (row == 0 && t == 0) out[0] = 0.0f;   // stream order: before pair_kernel

    const float* p  = preds + row * NN;
    const float* tv = targets + row * NN;

    unsigned u0 = __float_as_uint(p[t]);
    u0 = (u0 & 0x80000000u) ? ~u0 : (u0 | 0x80000000u);   // monotone asc
    ull v0 = ((ull)(~u0) << 32) | (ull)__float_as_uint(tv[t]);   // ~ => descending preds
    unsigned u1 = __float_as_uint(p[t + 1024]);
    u1 = (u1 & 0x80000000u) ? ~u1 : (u1 | 0x80000000u);
    ull v1 = ((ull)(~u1) << 32) | (ull)__float_as_uint(tv[t + 1024]);

    int cur = 0;
#pragma unroll
    for (int k = 2; k <= NN; k <<= 1) {
#pragma unroll
        for (int j = k >> 1; j > 0; j >>= 1) {
            if (j == 1024) {
                ull mn = (v0 < v1) ? v0 : v1;
                ull mx = (v0 < v1) ? v1 : v0;
                v0 = mn; v1 = mx;            // positions t (low) / t+1024 (high), ascending
            } else if (j >= 32) {
                sm[cur][t] = v0; sm[cur][t + 1024] = v1;
                __syncthreads();
                ull o0 = sm[cur][t ^ j];
                ull o1 = sm[cur][(t + 1024) ^ j];
                v0 = cex(v0, o0, t, j, k);
                v1 = cex(v1, o1, t + 1024, j, k);
                cur ^= 1;
            } else {
                ull o0 = __shfl_xor_sync(0xffffffffu, v0, j);
                v0 = cex(v0, o0, t, j, k);
                ull o1 = __shfl_xor_sync(0xffffffffu, v1, j);
                v1 = cex(v1, o1, t + 1024, j, k);
            }
        }
    }
    g_st[row * NN + t]        = __uint_as_float((unsigned)v0);
    g_st[row * NN + t + 1024] = __uint_as_float((unsigned)v1);
}

// ---------- kernel 2: triangle-tiled pair sum ----------
__global__ void __launch_bounds__(TS) pair_kernel(float* __restrict__ out) {
    __shared__ alignas(16) float ss[TS];   // targets of j-range
    __shared__ alignas(16) float dd[TS];   // dv of j-range
    __shared__ float wsum[TS / 32];

    const int row = blockIdx.y;

    // decode upper-triangle tile (ai <= ji) from linear index
    int ai = 0, rem = blockIdx.x;
    while (rem >= NT - ai) { rem -= NT - ai; ai++; }
    const int ji = ai + rem;

    const int tid = threadIdx.x;
    const float* st = g_st + row * NN;

    ss[tid] = st[ji * TS + tid];
    dd[tid] = __log2f((float)(ji * TS + tid + 3));

    const float ta = st[ai * TS + tid];
    const float da = __log2f((float)(ai * TS + tid + 3));
    const ull nta = pk2(-ta, -ta);
    __syncthreads();

    float res;
    if (ai != ji) {
        // all j in tile have dv_j > da: contribution = sum u*(dv_j - da)
        const ulonglong2* ps2 = (const ulonglong2*)ss;
        const ulonglong2* pd2 = (const ulonglong2*)dd;
        ull h0 = 0, h1 = 0, g0 = 0, g1 = 0;
#pragma unroll 8
        for (int j = 0; j < TS / 4; j++) {
            ulonglong2 s2 = ps2[j];
            ulonglong2 d2 = pd2[j];
            ull u = abs2(add2(s2.x, nta));
            h1 = fma2(u, d2.x, h1);
            h0 = add2(h0, u);
            ull w = abs2(add2(s2.y, nta));
            g1 = fma2(w, d2.y, g1);
            g0 = add2(g0, w);
        }
        res = (sum2(h1) + sum2(g1)) - da * (sum2(h0) + sum2(g0));
    } else {
        // diagonal tile: ordered pairs within tile via sign-split; scaled 0.5
        const ull* ps = (const ull*)ss;
        const ull* pd = (const ull*)dd;
        const int A = tid & ~1;
        ull l0 = 0, l1 = 0, h0 = 0, h1 = 0;
#pragma unroll 4
        for (int j = 0; j < (A >> 1); j++) {
            ull u = abs2(add2(ps[j], nta));
            l1 = fma2(u, pd[j], l1);
            l0 = add2(l0, u);
        }
#pragma unroll 4
        for (int j = (A >> 1); j < TS / 2; j++) {
            ull u = abs2(add2(ps[j], nta));
            h1 = fma2(u, pd[j], h1);
            h0 = add2(h0, u);
        }
        res = (sum2(h1) - sum2(l1)) + da * (sum2(l0) - sum2(h0));
        if (tid & 1) {
            float u = fabsf(ss[A] - ta);
            res += 2.0f * u * (da - dd[A]);
        }
        res *= 0.5f;
    }

    // block reduction
#pragma unroll
    for (int off = 16; off > 0; off >>= 1)
        res += __shfl_down_sync(0xffffffffu, res, off);
    if ((tid & 31) == 0) wsum[tid >> 5] = res;
    __syncthreads();
    if (tid == 0) {
        float bs = 0.f;
#pragma unroll
        for (int w = 0; w < TS / 32; w++) bs += wsum[w];
        atomicAdd(out, bs * (1.0f / (float)BB));
    }
}

extern "C" void kernel_launch(void* const* d_in, const int* in_sizes, int n_in,
                              void* d_out, int out_size) {
    const float* preds   = (const float*)d_in[0];
    const float* targets = (const float*)d_in[1];
    float* out = (float*)d_out;

    sort_kernel<<<BB, 1024>>>(preds, targets, out);

    dim3 grid(NTILES, BB);
    pair_kernel<<<grid, TS>>>(out);
}